// round 13
// baseline (speedup 1.0000x reference)
#include <cuda_runtime.h>
#include <math.h>
#include <stdint.h>

#define N_TOK 8192
#define D_DIM 1024
#define E_NUM 8
#define F_DIM 4096
#define K_CAP 1024

// ---- scratch (device globals: no allocation allowed) ----
__device__ float g_logits[N_TOK * E_NUM];
__device__ float g_probsT[E_NUM * N_TOK];
__device__ int   g_sel[E_NUM * K_CAP];
__device__ float g_wts[E_NUM * K_CAP];
__device__ float g_h  [(size_t)E_NUM * K_CAP * F_DIM];   // 128 MB (tf32-rounded)
__device__ float g_xr [(size_t)N_TOK * D_DIM];           // 32 MB
__device__ float g_w1r[(size_t)E_NUM * D_DIM * F_DIM];   // 128 MB
__device__ float g_w2r[(size_t)E_NUM * F_DIM * D_DIM];   // 128 MB

// ============================================================ helpers
__device__ __forceinline__ void cp16(uint32_t dst, const void* src) {
    asm volatile("cp.async.cg.shared.global [%0], [%1], 16;" :: "r"(dst), "l"(src));
}
__device__ __forceinline__ uint32_t smem_u32(const void* p) {
    uint32_t a;
    asm("{ .reg .u64 t; cvta.to.shared.u64 t, %1; cvt.u32.u64 %0, t; }"
        : "=r"(a) : "l"(p));
    return a;
}
__device__ __forceinline__ float to_tf32(float f) {
    float r; asm("cvt.rna.tf32.f32 %0, %1;" : "=f"(r) : "f"(f)); return r;
}
__device__ __forceinline__ void mma1688(float* c, const uint32_t* a, const uint32_t* b) {
    asm volatile(
        "mma.sync.aligned.m16n8k8.row.col.f32.tf32.tf32.f32 "
        "{%0,%1,%2,%3}, {%4,%5,%6,%7}, {%8,%9}, {%0,%1,%2,%3};"
        : "+f"(c[0]), "+f"(c[1]), "+f"(c[2]), "+f"(c[3])
        : "r"(a[0]), "r"(a[1]), "r"(a[2]), "r"(a[3]), "r"(b[0]), "r"(b[1]));
}

// ============================================================
// K0: elementwise tf32 rounding (grid-stride float4)
// ============================================================
__global__ void cvt_round_kernel(const float* __restrict__ src,
                                 float* __restrict__ dst, size_t n4) {
    size_t stride = (size_t)gridDim.x * blockDim.x;
    for (size_t i = (size_t)blockIdx.x * blockDim.x + threadIdx.x; i < n4; i += stride) {
        float4 v = ((const float4*)src)[i];
        v.x = to_tf32(v.x); v.y = to_tf32(v.y);
        v.z = to_tf32(v.z); v.w = to_tf32(v.w);
        ((float4*)dst)[i] = v;
    }
}

// ============================================================
// K1: router logits + softmax. One block per token, float4 single pass.
// ============================================================
__global__ void router_kernel(const float* __restrict__ x,
                              const float* __restrict__ rw) {
    int t = blockIdx.x;
    int tid = threadIdx.x;
    float4 xv = ((const float4*)(x + (size_t)t * D_DIM))[tid];
    float acc[E_NUM];
#pragma unroll
    for (int e = 0; e < E_NUM; e++) {
        float4 wv = ((const float4*)(rw + (size_t)e * D_DIM))[tid];
        float s = xv.x * wv.x;
        s = fmaf(xv.y, wv.y, s);
        s = fmaf(xv.z, wv.z, s);
        acc[e] = fmaf(xv.w, wv.w, s);
    }
    __shared__ float red[E_NUM * 256];
#pragma unroll
    for (int e = 0; e < E_NUM; e++) red[e * 256 + tid] = acc[e];
    __syncthreads();
    for (int s = 128; s > 0; s >>= 1) {
        if (tid < s) {
#pragma unroll
            for (int e = 0; e < E_NUM; e++)
                red[e * 256 + tid] += red[e * 256 + tid + s];
        }
        __syncthreads();
    }
    if (tid == 0) {
        float l[E_NUM];
        float mx = -1e30f;
#pragma unroll
        for (int e = 0; e < E_NUM; e++) {
            l[e] = red[e * 256];
            g_logits[t * E_NUM + e] = l[e];
            mx = fmaxf(mx, l[e]);
        }
        float s = 0.0f;
#pragma unroll
        for (int e = 0; e < E_NUM; e++) { l[e] = expf(l[e] - mx); s += l[e]; }
        float inv = 1.0f / s;
#pragma unroll
        for (int e = 0; e < E_NUM; e++)
            g_probsT[e * N_TOK + t] = l[e] * inv;
    }
}

// ============================================================
// K2: per-expert top-K via radix-select + small bitonic of winners.
// ============================================================
#define TOPK_BINS 4096
__global__ void topk_select_kernel() {
    extern __shared__ unsigned long long cand[];
    __shared__ unsigned hist[TOPK_BINS];
    __shared__ unsigned suf[1024];
    __shared__ unsigned long long outk[K_CAP];
    __shared__ unsigned s_binB, s_need, s_ncand, s_slot, s_coarse;

    int e = blockIdx.x, tid = threadIdx.x;
    const float* p = g_probsT + (size_t)e * N_TOK;

#pragma unroll
    for (int i = 0; i < TOPK_BINS / 1024; i++) hist[tid + i * 1024] = 0;
    if (tid == 0) { s_ncand = 0; s_slot = 0; s_coarse = 0; }
    __syncthreads();

    unsigned fb[8];
#pragma unroll
    for (int k = 0; k < 8; k++) {
        int i = tid + k * 1024;
        fb[k] = __float_as_uint(p[i]);
        atomicAdd(&hist[fb[k] >> 20], 1u);
    }
    __syncthreads();

    unsigned s = hist[4 * tid] + hist[4 * tid + 1] + hist[4 * tid + 2] + hist[4 * tid + 3];
    suf[tid] = s;
    __syncthreads();
    for (int off = 1; off < 1024; off <<= 1) {
        unsigned v = (tid + off < 1024) ? suf[tid + off] : 0;
        __syncthreads();
        suf[tid] += v;
        __syncthreads();
    }
    if (suf[tid] >= K_CAP && (tid == 1023 || suf[tid + 1] < K_CAP)) s_coarse = tid;
    __syncthreads();
    if (tid == 0) {
        unsigned co = s_coarse;
        unsigned above = (co == 1023) ? 0 : suf[co + 1];
        unsigned B = 4 * co, need = 0;
        for (int b = 4 * (int)co + 3; b >= 4 * (int)co; b--) {
            if (above + hist[b] >= K_CAP) { B = (unsigned)b; need = K_CAP - above; break; }
            above += hist[b];
        }
        s_binB = B; s_need = need;
    }
    __syncthreads();
    unsigned B = s_binB, need = s_need;

#pragma unroll
    for (int k = 0; k < 8; k++) {
        int i = tid + k * 1024;
        unsigned b = fb[k] >> 20;
        unsigned long long key =
            ((unsigned long long)fb[k] << 32) | (unsigned)(0xFFFFFFFFu - (unsigned)i);
        if (b > B) {
            unsigned sl = atomicAdd(&s_slot, 1u);
            outk[sl] = key;
        } else if (b == B) {
            unsigned c = atomicAdd(&s_ncand, 1u);
            cand[c] = key;
        }
    }
    __syncthreads();
    unsigned c = s_ncand;
    for (unsigned j = tid; j < c; j += 1024) {
        unsigned long long kj = cand[j];
        unsigned rank = 0;
        for (unsigned l = 0; l < c; l++) rank += (cand[l] > kj);
        if (rank < need) {
            unsigned sl = atomicAdd(&s_slot, 1u);
            outk[sl] = kj;
        }
    }
    __syncthreads();

    for (int k = 2; k <= K_CAP; k <<= 1) {
        for (int j = k >> 1; j > 0; j >>= 1) {
            int ixj = tid ^ j;
            if (ixj > tid) {
                unsigned long long a = outk[tid], bk = outk[ixj];
                bool desc = ((tid & k) == 0);
                if (desc ? (a < bk) : (a > bk)) { outk[tid] = bk; outk[ixj] = a; }
            }
            __syncthreads();
        }
    }
    unsigned long long a = outk[tid];
    g_wts[e * K_CAP + tid] = __uint_as_float((unsigned)(a >> 32));
    g_sel[e * K_CAP + tid] = (int)(0xFFFFFFFFu - (unsigned)(a & 0xFFFFFFFFu));
}

// ============================================================
// tf32 mma.sync GEMM: CTA 128x128, 4 warps (2x2), warp tile 64x64,
// k-tile 16, 5-stage cp.async pipeline,
// register double-buffered fragments (prefetch next k-group during MMAs,
// including across the k-tile boundary into the next smem stage).
// ============================================================
#define A_STRIDE 20
#define B_STRIDE 136
#define A_SZ (128 * A_STRIDE * 4)        // 10240 B
#define B_SZ (16 * B_STRIDE * 4)         // 8704 B
#define STG_SZ (A_SZ + B_SZ)             // 18944 B
#define NSTAGE 5
#define SMEM_DYN (NSTAGE * STG_SZ)       // 94720 B

template <int KDIM, int NDIM, bool IS_G1>
__global__ __launch_bounds__(128, 2) void moe_gemm_kernel(
    const float* __restrict__ A_src, const float* __restrict__ B_src,
    const float* __restrict__ bias, float* __restrict__ out) {
    constexpr int KT = KDIM / 16;

    extern __shared__ char smem[];
    uint32_t sb = smem_u32(smem);
    const uint32_t* smu = (const uint32_t*)smem;

    int e = blockIdx.z, m0 = blockIdx.y * 128, n0 = blockIdx.x * 128;
    int t = threadIdx.x, wid = t >> 5, lane = t & 31;
    int wm = (wid >> 1) * 64, wn = (wid & 1) * 64;

    // cp.async: A 128x16 (512 chunks), B 16x128 (512 chunks), 8 per thread
    int rA = t >> 2, kcA = t & 3;
    int krB = t >> 5, ncB = t & 31;
    const float* aptr[4];
#pragma unroll
    for (int i = 0; i < 4; i++) {
        int r = rA + 32 * i;
        size_t row;
        if (IS_G1) row = (size_t)g_sel[e * K_CAP + m0 + r];
        else       row = (size_t)e * K_CAP + m0 + r;
        aptr[i] = A_src + row * KDIM + kcA * 4;
    }
    const float* bptr[4];
#pragma unroll
    for (int j = 0; j < 4; j++)
        bptr[j] = B_src + (size_t)e * KDIM * NDIM + (size_t)(krB + 4 * j) * NDIM + n0 + ncB * 4;
    uint32_t adst[4], bdst[4];
#pragma unroll
    for (int i = 0; i < 4; i++)
        adst[i] = sb + (uint32_t)(rA + 32 * i) * (A_STRIDE * 4) + kcA * 16;
#pragma unroll
    for (int j = 0; j < 4; j++)
        bdst[j] = sb + A_SZ + (uint32_t)(krB + 4 * j) * (B_STRIDE * 4) + ncB * 16;

#define LOAD_STAGE(SLOT, KTILE)                                                 \
    do {                                                                        \
        uint32_t off = (uint32_t)(SLOT) * STG_SZ;                               \
        size_t ka = (size_t)(KTILE) * 16;                                       \
        size_t kb = (size_t)(KTILE) * 16 * NDIM;                                \
        _Pragma("unroll")                                                       \
        for (int i = 0; i < 4; i++) cp16(adst[i] + off, aptr[i] + ka);          \
        _Pragma("unroll")                                                       \
        for (int j = 0; j < 4; j++) cp16(bdst[j] + off, bptr[j] + kb);          \
        asm volatile("cp.async.commit_group;");                                 \
    } while (0)

#define LOAD_FRAGS(af, bf, As, Bs, KK)                                          \
    do {                                                                        \
        _Pragma("unroll")                                                       \
        for (int mi = 0; mi < 4; mi++) {                                        \
            int row = wm + mi * 16 + lg;                                        \
            (af)[mi][0] = (As)[row * A_STRIDE + (KK)];                          \
            (af)[mi][1] = (As)[(row + 8) * A_STRIDE + (KK)];                    \
            (af)[mi][2] = (As)[row * A_STRIDE + (KK) + 4];                      \
            (af)[mi][3] = (As)[(row + 8) * A_STRIDE + (KK) + 4];                \
        }                                                                       \
        _Pragma("unroll")                                                       \
        for (int ni = 0; ni < 8; ni++) {                                        \
            int col = wn + ni * 8 + lg;                                         \
            (bf)[ni][0] = (Bs)[(KK) * B_STRIDE + col];                          \
            (bf)[ni][1] = (Bs)[((KK) + 4) * B_STRIDE + col];                    \
        }                                                                       \
    } while (0)

#define MMA_ALL(af, bf)                                                         \
    do {                                                                        \
        _Pragma("unroll")                                                       \
        for (int mi = 0; mi < 4; mi++)                                          \
            _Pragma("unroll")                                                   \
            for (int ni = 0; ni < 8; ni++)                                      \
                mma1688(acc[mi][ni], (af)[mi], (bf)[ni]);                       \
    } while (0)

    float acc[4][8][4];
#pragma unroll
    for (int mi = 0; mi < 4; mi++)
#pragma unroll
        for (int ni = 0; ni < 8; ni++)
#pragma unroll
            for (int r = 0; r < 4; r++) acc[mi][ni][r] = 0.0f;

    LOAD_STAGE(0, 0); LOAD_STAGE(1, 1); LOAD_STAGE(2, 2); LOAD_STAGE(3, 3);

    int lg = lane >> 2, lt = lane & 3;

    // stages 0 and 1 complete (4 committed, <=2 pending)
    asm volatile("cp.async.wait_group 2;");
    __syncthreads();

    uint32_t fa0[4][4], fb0[8][2], fa1[4][4], fb1[8][2];
    LOAD_FRAGS(fa0, fb0, smu, smu + A_SZ / 4, lt);   // (kt=0, g0)

    int cur = 0;
#pragma unroll 1
    for (int kt = 0; kt < KT; kt++) {
        if (kt + NSTAGE - 1 < KT) {
            int slot = (kt + NSTAGE - 1) % NSTAGE;
            LOAD_STAGE(slot, kt + NSTAGE - 1);
        }
        int nstg = (cur + 1 == NSTAGE) ? 0 : cur + 1;
        const uint32_t* As  = smu + (size_t)cur  * (STG_SZ / 4);
        const uint32_t* Bs  = As + A_SZ / 4;
        const uint32_t* Asn = smu + (size_t)nstg * (STG_SZ / 4);
        const uint32_t* Bsn = Asn + A_SZ / 4;

        // g0: prefetch g1 of this tile, compute with fa0/fb0
        LOAD_FRAGS(fa1, fb1, As, Bs, 8 + lt);
        MMA_ALL(fa0, fb0);
        // g1: prefetch g0 of NEXT tile (next stage; garbage at last kt, unused),
        //     compute with fa1/fb1
        LOAD_FRAGS(fa0, fb0, Asn, Bsn, lt);
        MMA_ALL(fa1, fb1);

        if (kt < KT - 1) {
            // ensure stage kt+2 complete before next iteration's cross-tile
            // prefetch; also gates slot reuse (slot kt%NSTAGE rewritten at kt+1)
            int rem = KT - 3 - kt;   // allowed pending groups
            if (rem >= 2)      asm volatile("cp.async.wait_group 2;");
            else if (rem == 1) asm volatile("cp.async.wait_group 1;");
            else               asm volatile("cp.async.wait_group 0;");
            __syncthreads();
        }
        cur = nstg;
    }
#undef LOAD_STAGE
#undef LOAD_FRAGS
#undef MMA_ALL

    // ---- epilogue ----
    if (IS_G1) {
#pragma unroll
        for (int mi = 0; mi < 4; mi++) {
            int m = m0 + wm + mi * 16 + lg;
#pragma unroll
            for (int ni = 0; ni < 8; ni++) {
                int n = n0 + wn + ni * 8 + 2 * lt;
                float b0 = bias[(size_t)e * NDIM + n];
                float b1v = bias[(size_t)e * NDIM + n + 1];
#pragma unroll
                for (int half = 0; half < 2; half++) {
                    int mm = m + half * 8;
                    float v0 = acc[mi][ni][half * 2 + 0] + b0;
                    float v1 = acc[mi][ni][half * 2 + 1] + b1v;
                    v0 = 0.5f * v0 * (1.0f + erff(v0 * 0.70710678118654752f));
                    v1 = 0.5f * v1 * (1.0f + erff(v1 * 0.70710678118654752f));
                    float2 v = make_float2(to_tf32(v0), to_tf32(v1));
                    *(float2*)(out + ((size_t)e * K_CAP + mm) * F_DIM + n) = v;
                }
            }
        }
    } else {
#pragma unroll
        for (int mi = 0; mi < 4; mi++) {
            int m = m0 + wm + mi * 16 + lg;
            int tok0 = g_sel[e * K_CAP + m];
            int tok1 = g_sel[e * K_CAP + m + 8];
            float w0 = g_wts[e * K_CAP + m];
            float w1v = g_wts[e * K_CAP + m + 8];
#pragma unroll
            for (int ni = 0; ni < 8; ni++) {
                int n = n0 + wn + ni * 8 + 2 * lt;
                float b0 = bias[(size_t)e * NDIM + n];
                float b1v = bias[(size_t)e * NDIM + n + 1];
                atomicAdd(out + (size_t)tok0 * D_DIM + n,     (acc[mi][ni][0] + b0) * w0);
                atomicAdd(out + (size_t)tok0 * D_DIM + n + 1, (acc[mi][ni][1] + b1v) * w0);
                atomicAdd(out + (size_t)tok1 * D_DIM + n,     (acc[mi][ni][2] + b0) * w1v);
                atomicAdd(out + (size_t)tok1 * D_DIM + n + 1, (acc[mi][ni][3] + b1v) * w1v);
            }
        }
    }
}

// ============================================================
// K5: optional extra outputs
// ============================================================
__global__ void tail_kernel(float* __restrict__ out, int mode) {
    int i = blockIdx.x * 256 + threadIdx.x;
    const int R = N_TOK * D_DIM;
    if (mode >= 1 && i < N_TOK * E_NUM) out[R + i] = g_logits[i];
    if (mode >= 2 && i < E_NUM * K_CAP) out[R + N_TOK * E_NUM + i] = (float)g_sel[i];
}

extern "C" void kernel_launch(void* const* d_in, const int* in_sizes, int n_in,
                              void* d_out, int out_size) {
    const float* x  = (const float*)d_in[0];
    const float* rw = (const float*)d_in[1];
    const float* w1 = (const float*)d_in[2];
    const float* b1 = (const float*)d_in[3];
    const float* w2 = (const float*)d_in[4];
    const float* b2 = (const float*)d_in[5];
    float* out = (float*)d_out;

    cudaMemsetAsync(out, 0, (size_t)N_TOK * D_DIM * sizeof(float), 0);

    float *xr, *w1r, *w2r, *h;
    cudaGetSymbolAddress((void**)&xr,  g_xr);
    cudaGetSymbolAddress((void**)&w1r, g_w1r);
    cudaGetSymbolAddress((void**)&w2r, g_w2r);
    cudaGetSymbolAddress((void**)&h,   g_h);

    // staging: tf32-round x, w1, w2 (elementwise, no transpose)
    cvt_round_kernel<<<2048, 256>>>(x,  xr,  (size_t)N_TOK * D_DIM / 4);
    cvt_round_kernel<<<8192, 256>>>(w1, w1r, (size_t)E_NUM * D_DIM * F_DIM / 4);
    cvt_round_kernel<<<8192, 256>>>(w2, w2r, (size_t)E_NUM * F_DIM * D_DIM / 4);

    router_kernel<<<N_TOK, 256>>>(x, rw);

    cudaFuncSetAttribute(topk_select_kernel, cudaFuncAttributeMaxDynamicSharedMemorySize,
                         N_TOK * sizeof(unsigned long long));
    topk_select_kernel<<<E_NUM, 1024, N_TOK * sizeof(unsigned long long)>>>();

    cudaFuncSetAttribute((const void*)moe_gemm_kernel<D_DIM, F_DIM, true>,
                         cudaFuncAttributeMaxDynamicSharedMemorySize, SMEM_DYN);
    cudaFuncSetAttribute((const void*)moe_gemm_kernel<F_DIM, D_DIM, false>,
                         cudaFuncAttributeMaxDynamicSharedMemorySize, SMEM_DYN);

    // GEMM1: h = tf32round(gelu(gather(xr) @ w1r + b1))
    moe_gemm_kernel<D_DIM, F_DIM, true>
        <<<dim3(F_DIM / 128, K_CAP / 128, E_NUM), 128, SMEM_DYN>>>(xr, w1r, b1, h);
    // GEMM2: out += scatter((h @ w2r + b2) * wts)
    moe_gemm_kernel<F_DIM, D_DIM, false>
        <<<dim3(D_DIM / 128, K_CAP / 128, E_NUM), 128, SMEM_DYN>>>(h, w2r, b2, out);

    const int R = N_TOK * D_DIM;
    if (out_size >= R + N_TOK * E_NUM) {
        int mode = (out_size >= R + N_TOK * E_NUM + E_NUM * K_CAP) ? 2 : 1;
        tail_kernel<<<(N_TOK * E_NUM + 255) / 256, 256>>>(out, mode);
    }
}

// round 14
// speedup vs baseline: 1.4961x; 1.4961x over previous
#include <cuda_runtime.h>
#include <cuda_fp16.h>
#include <math.h>
#include <stdint.h>

#define N_TOK 8192
#define D_DIM 1024
#define E_NUM 8
#define F_DIM 4096
#define K_CAP 1024

// ---- scratch (device globals: no allocation allowed) ----
__device__ float  g_logits[N_TOK * E_NUM];
__device__ float  g_probsT[E_NUM * N_TOK];
__device__ int    g_sel[E_NUM * K_CAP];
__device__ float  g_wts[E_NUM * K_CAP];
__device__ __half g_xh [(size_t)N_TOK * D_DIM];           // 16 MB
__device__ __half g_w1t[(size_t)E_NUM * F_DIM * D_DIM];   // 64 MB  [e][f][d]
__device__ __half g_w2t[(size_t)E_NUM * D_DIM * F_DIM];   // 64 MB  [e][d][f]
__device__ __half g_hh [(size_t)E_NUM * K_CAP * F_DIM];   // 64 MB  [e][k][f]

// ============================================================ helpers
__device__ __forceinline__ void cp16(uint32_t dst, const void* src) {
    asm volatile("cp.async.cg.shared.global [%0], [%1], 16;" :: "r"(dst), "l"(src));
}
__device__ __forceinline__ uint32_t smem_u32(const void* p) {
    uint32_t a;
    asm("{ .reg .u64 t; cvta.to.shared.u64 t, %1; cvt.u32.u64 %0, t; }"
        : "=r"(a) : "l"(p));
    return a;
}
__device__ __forceinline__ void mma16816(float* c, const uint32_t* a, const uint32_t* b) {
    asm volatile(
        "mma.sync.aligned.m16n8k16.row.col.f32.f16.f16.f32 "
        "{%0,%1,%2,%3}, {%4,%5,%6,%7}, {%8,%9}, {%0,%1,%2,%3};"
        : "+f"(c[0]), "+f"(c[1]), "+f"(c[2]), "+f"(c[3])
        : "r"(a[0]), "r"(a[1]), "r"(a[2]), "r"(a[3]), "r"(b[0]), "r"(b[1]));
}

// ============================================================
// K0a: x f32 -> fp16 (grid-stride float4 -> half4)
// ============================================================
__global__ void cvt_x_f16_kernel(const float* __restrict__ src) {
    size_t stride = (size_t)gridDim.x * blockDim.x;
    size_t n4 = (size_t)N_TOK * D_DIM / 4;
    for (size_t i = (size_t)blockIdx.x * blockDim.x + threadIdx.x; i < n4; i += stride) {
        float4 v = ((const float4*)src)[i];
        __half2 h0 = __floats2half2_rn(v.x, v.y);
        __half2 h1 = __floats2half2_rn(v.z, v.w);
        ((__half2*)g_xh)[2 * i]     = h0;
        ((__half2*)g_xh)[2 * i + 1] = h1;
    }
}

// ============================================================
// K0b: transpose + cvt to fp16: src [E][R][C] f32 -> dst [E][C][R] half
// ============================================================
__global__ void transpose_cvt_f16_kernel(const float* __restrict__ src,
                                         __half* __restrict__ dst, int R, int C) {
    __shared__ float tile[32][33];
    int e = blockIdx.z;
    int c0 = blockIdx.x * 32, r0 = blockIdx.y * 32;
    const float* s = src + (size_t)e * R * C;
    __half* d = dst + (size_t)e * C * R;
    int tx = threadIdx.x, ty = threadIdx.y;
#pragma unroll
    for (int i = 0; i < 32; i += 8)
        tile[ty + i][tx] = s[(size_t)(r0 + ty + i) * C + c0 + tx];
    __syncthreads();
#pragma unroll
    for (int i = 0; i < 32; i += 8)
        d[(size_t)(c0 + ty + i) * R + r0 + tx] = __float2half_rn(tile[tx][ty + i]);
}

// ============================================================
// K1: router logits + softmax. One block per token, float4 single pass.
// ============================================================
__global__ void router_kernel(const float* __restrict__ x,
                              const float* __restrict__ rw) {
    int t = blockIdx.x;
    int tid = threadIdx.x;
    float4 xv = ((const float4*)(x + (size_t)t * D_DIM))[tid];
    float acc[E_NUM];
#pragma unroll
    for (int e = 0; e < E_NUM; e++) {
        float4 wv = ((const float4*)(rw + (size_t)e * D_DIM))[tid];
        float s = xv.x * wv.x;
        s = fmaf(xv.y, wv.y, s);
        s = fmaf(xv.z, wv.z, s);
        acc[e] = fmaf(xv.w, wv.w, s);
    }
    __shared__ float red[E_NUM * 256];
#pragma unroll
    for (int e = 0; e < E_NUM; e++) red[e * 256 + tid] = acc[e];
    __syncthreads();
    for (int s = 128; s > 0; s >>= 1) {
        if (tid < s) {
#pragma unroll
            for (int e = 0; e < E_NUM; e++)
                red[e * 256 + tid] += red[e * 256 + tid + s];
        }
        __syncthreads();
    }
    if (tid == 0) {
        float l[E_NUM];
        float mx = -1e30f;
#pragma unroll
        for (int e = 0; e < E_NUM; e++) {
            l[e] = red[e * 256];
            g_logits[t * E_NUM + e] = l[e];
            mx = fmaxf(mx, l[e]);
        }
        float s = 0.0f;
#pragma unroll
        for (int e = 0; e < E_NUM; e++) { l[e] = expf(l[e] - mx); s += l[e]; }
        float inv = 1.0f / s;
#pragma unroll
        for (int e = 0; e < E_NUM; e++)
            g_probsT[e * N_TOK + t] = l[e] * inv;
    }
}

// ============================================================
// K2: per-expert top-K via radix-select + small bitonic of winners.
// ============================================================
#define TOPK_BINS 4096
__global__ void topk_select_kernel() {
    extern __shared__ unsigned long long cand[];
    __shared__ unsigned hist[TOPK_BINS];
    __shared__ unsigned suf[1024];
    __shared__ unsigned long long outk[K_CAP];
    __shared__ unsigned s_binB, s_need, s_ncand, s_slot, s_coarse;

    int e = blockIdx.x, tid = threadIdx.x;
    const float* p = g_probsT + (size_t)e * N_TOK;

#pragma unroll
    for (int i = 0; i < TOPK_BINS / 1024; i++) hist[tid + i * 1024] = 0;
    if (tid == 0) { s_ncand = 0; s_slot = 0; s_coarse = 0; }
    __syncthreads();

    unsigned fb[8];
#pragma unroll
    for (int k = 0; k < 8; k++) {
        int i = tid + k * 1024;
        fb[k] = __float_as_uint(p[i]);
        atomicAdd(&hist[fb[k] >> 20], 1u);
    }
    __syncthreads();

    unsigned s = hist[4 * tid] + hist[4 * tid + 1] + hist[4 * tid + 2] + hist[4 * tid + 3];
    suf[tid] = s;
    __syncthreads();
    for (int off = 1; off < 1024; off <<= 1) {
        unsigned v = (tid + off < 1024) ? suf[tid + off] : 0;
        __syncthreads();
        suf[tid] += v;
        __syncthreads();
    }
    if (suf[tid] >= K_CAP && (tid == 1023 || suf[tid + 1] < K_CAP)) s_coarse = tid;
    __syncthreads();
    if (tid == 0) {
        unsigned co = s_coarse;
        unsigned above = (co == 1023) ? 0 : suf[co + 1];
        unsigned B = 4 * co, need = 0;
        for (int b = 4 * (int)co + 3; b >= 4 * (int)co; b--) {
            if (above + hist[b] >= K_CAP) { B = (unsigned)b; need = K_CAP - above; break; }
            above += hist[b];
        }
        s_binB = B; s_need = need;
    }
    __syncthreads();
    unsigned B = s_binB, need = s_need;

#pragma unroll
    for (int k = 0; k < 8; k++) {
        int i = tid + k * 1024;
        unsigned b = fb[k] >> 20;
        unsigned long long key =
            ((unsigned long long)fb[k] << 32) | (unsigned)(0xFFFFFFFFu - (unsigned)i);
        if (b > B) {
            unsigned sl = atomicAdd(&s_slot, 1u);
            outk[sl] = key;
        } else if (b == B) {
            unsigned c = atomicAdd(&s_ncand, 1u);
            cand[c] = key;
        }
    }
    __syncthreads();
    unsigned c = s_ncand;
    for (unsigned j = tid; j < c; j += 1024) {
        unsigned long long kj = cand[j];
        unsigned rank = 0;
        for (unsigned l = 0; l < c; l++) rank += (cand[l] > kj);
        if (rank < need) {
            unsigned sl = atomicAdd(&s_slot, 1u);
            outk[sl] = kj;
        }
    }
    __syncthreads();

    for (int k = 2; k <= K_CAP; k <<= 1) {
        for (int j = k >> 1; j > 0; j >>= 1) {
            int ixj = tid ^ j;
            if (ixj > tid) {
                unsigned long long a = outk[tid], bk = outk[ixj];
                bool desc = ((tid & k) == 0);
                if (desc ? (a < bk) : (a > bk)) { outk[tid] = bk; outk[ixj] = a; }
            }
            __syncthreads();
        }
    }
    unsigned long long a = outk[tid];
    g_wts[e * K_CAP + tid] = __uint_as_float((unsigned)(a >> 32));
    g_sel[e * K_CAP + tid] = (int)(0xFFFFFFFFu - (unsigned)(a & 0xFFFFFFFFu));
}

// ============================================================
// fp16 mma.sync GEMM: CTA 128x128, 4 warps (2x2), warp tile 64x64,
// mma.m16n8k16.f16 (f32 accum), k-tile 32, 4-stage cp.async pipeline.
// SMEM: A and B both K-major fp16 rows of 32 halves (64B),
// 16B-chunk XOR swizzle (c ^ ((row>>1)&3)) -> conflict-free frag LDS.
// A rounds to fp16 via staging; B pre-transposed fp16 [n][k].
// ============================================================
#define STG_BYTES 16384                 // A 8KB + B 8KB
#define NSTAGE 4
#define SMEM_DYN (NSTAGE * STG_BYTES)   // 65536 B

template <int KDIM, int NDIM, bool IS_G1>
__global__ __launch_bounds__(128, 2) void moe_gemm_kernel(
    const __half* __restrict__ A_src, const __half* __restrict__ B_src,
    const float* __restrict__ bias, float* __restrict__ out,
    __half* __restrict__ hout) {
    constexpr int KT = KDIM / 32;

    extern __shared__ char smem[];
    uint32_t sb = smem_u32(smem);
    const uint32_t* smu = (const uint32_t*)smem;

    int e = blockIdx.z, m0 = blockIdx.y * 128, n0 = blockIdx.x * 128;
    int t = threadIdx.x, wid = t >> 5, lane = t & 31;
    int wm = (wid >> 1) * 64, wn = (wid & 1) * 64;
    int lg = lane >> 2, lt = lane & 3;

    // ---- cp.async: thread t owns A row t and B row t (4 chunks of 16B each)
    const __half* aptr;
    if (IS_G1) aptr = A_src + (size_t)g_sel[e * K_CAP + m0 + t] * KDIM;
    else       aptr = A_src + ((size_t)e * K_CAP + m0 + t) * KDIM;
    const __half* bptr = B_src + ((size_t)e * NDIM + n0 + t) * KDIM;
    uint32_t swz[4];
    {
        uint32_t xt = ((uint32_t)t >> 1) & 3;
#pragma unroll
        for (int c = 0; c < 4; c++)
            swz[c] = (uint32_t)t * 64 + (((uint32_t)c ^ xt) << 4);
    }

#define LOAD_STAGE(SLOT, KTILE)                                                 \
    do {                                                                        \
        uint32_t off = (uint32_t)(SLOT) * STG_BYTES;                            \
        size_t kh = (size_t)(KTILE) * 32;                                       \
        _Pragma("unroll")                                                       \
        for (int c = 0; c < 4; c++)                                             \
            cp16(sb + off + swz[c], aptr + kh + c * 8);                         \
        _Pragma("unroll")                                                       \
        for (int c = 0; c < 4; c++)                                             \
            cp16(sb + off + 8192 + swz[c], bptr + kh + c * 8);                  \
        asm volatile("cp.async.commit_group;");                                 \
    } while (0)

    // fragment base word-indices (stage-relative, u32 units; row = 16 words)
    uint32_t wbase[4], bbase[8];
#pragma unroll
    for (int mi = 0; mi < 4; mi++) wbase[mi] = (uint32_t)(wm + mi * 16 + lg) * 16 + lt;
#pragma unroll
    for (int ni = 0; ni < 8; ni++) bbase[ni] = (uint32_t)(wn + ni * 8 + lg) * 16 + lt;
    uint32_t xk = ((uint32_t)lg >> 1) & 3;     // same for all rows/cols used

    float acc[4][8][4];
#pragma unroll
    for (int mi = 0; mi < 4; mi++)
#pragma unroll
        for (int ni = 0; ni < 8; ni++)
#pragma unroll
            for (int r = 0; r < 4; r++) acc[mi][ni][r] = 0.0f;

    LOAD_STAGE(0, 0); LOAD_STAGE(1, 1); LOAD_STAGE(2, 2);

#pragma unroll 1
    for (int kt = 0; kt < KT; kt++) {
        int rem = KT - 1 - kt;
        if (rem >= 2)      asm volatile("cp.async.wait_group 2;");
        else if (rem == 1) asm volatile("cp.async.wait_group 1;");
        else               asm volatile("cp.async.wait_group 0;");
        __syncthreads();
        if (kt + NSTAGE - 1 < KT) LOAD_STAGE((kt + NSTAGE - 1) & (NSTAGE - 1), kt + NSTAGE - 1);

        const uint32_t* As = smu + (size_t)(kt & (NSTAGE - 1)) * (STG_BYTES / 4);
        const uint32_t* Bs = As + 2048;

#pragma unroll
        for (int g = 0; g < 2; g++) {
            uint32_t ca = ((uint32_t)(2 * g)) ^ xk;
            uint32_t cb = ca ^ 1u;
            uint32_t af[4][4], bf[8][2];
#pragma unroll
            for (int mi = 0; mi < 4; mi++) {
                af[mi][0] = As[wbase[mi] + 4 * ca];
                af[mi][1] = As[wbase[mi] + 128 + 4 * ca];
                af[mi][2] = As[wbase[mi] + 4 * cb];
                af[mi][3] = As[wbase[mi] + 128 + 4 * cb];
            }
#pragma unroll
            for (int ni = 0; ni < 8; ni++) {
                bf[ni][0] = Bs[bbase[ni] + 4 * ca];
                bf[ni][1] = Bs[bbase[ni] + 4 * cb];
            }
#pragma unroll
            for (int mi = 0; mi < 4; mi++)
#pragma unroll
                for (int ni = 0; ni < 8; ni++)
                    mma16816(acc[mi][ni], af[mi], bf[ni]);
        }
    }
#undef LOAD_STAGE

    // ---- epilogue ----
    if (IS_G1) {
#pragma unroll
        for (int mi = 0; mi < 4; mi++) {
            int m = m0 + wm + mi * 16 + lg;
#pragma unroll
            for (int ni = 0; ni < 8; ni++) {
                int n = n0 + wn + ni * 8 + 2 * lt;
                float b0 = bias[(size_t)e * NDIM + n];
                float b1v = bias[(size_t)e * NDIM + n + 1];
#pragma unroll
                for (int half = 0; half < 2; half++) {
                    int mm = m + half * 8;
                    float v0 = acc[mi][ni][half * 2 + 0] + b0;
                    float v1 = acc[mi][ni][half * 2 + 1] + b1v;
                    v0 = 0.5f * v0 * (1.0f + erff(v0 * 0.70710678118654752f));
                    v1 = 0.5f * v1 * (1.0f + erff(v1 * 0.70710678118654752f));
                    __half2 hv = __floats2half2_rn(v0, v1);
                    *(__half2*)(hout + ((size_t)e * K_CAP + mm) * F_DIM + n) = hv;
                }
            }
        }
    } else {
#pragma unroll
        for (int mi = 0; mi < 4; mi++) {
            int m = m0 + wm + mi * 16 + lg;
            int tok0 = g_sel[e * K_CAP + m];
            int tok1 = g_sel[e * K_CAP + m + 8];
            float w0 = g_wts[e * K_CAP + m];
            float w1v = g_wts[e * K_CAP + m + 8];
#pragma unroll
            for (int ni = 0; ni < 8; ni++) {
                int n = n0 + wn + ni * 8 + 2 * lt;
                float b0 = bias[(size_t)e * NDIM + n];
                float b1v = bias[(size_t)e * NDIM + n + 1];
                atomicAdd(out + (size_t)tok0 * D_DIM + n,     (acc[mi][ni][0] + b0) * w0);
                atomicAdd(out + (size_t)tok0 * D_DIM + n + 1, (acc[mi][ni][1] + b1v) * w0);
                atomicAdd(out + (size_t)tok1 * D_DIM + n,     (acc[mi][ni][2] + b0) * w1v);
                atomicAdd(out + (size_t)tok1 * D_DIM + n + 1, (acc[mi][ni][3] + b1v) * w1v);
            }
        }
    }
}

// ============================================================
// K5: optional extra outputs
// ============================================================
__global__ void tail_kernel(float* __restrict__ out, int mode) {
    int i = blockIdx.x * 256 + threadIdx.x;
    const int R = N_TOK * D_DIM;
    if (mode >= 1 && i < N_TOK * E_NUM) out[R + i] = g_logits[i];
    if (mode >= 2 && i < E_NUM * K_CAP) out[R + N_TOK * E_NUM + i] = (float)g_sel[i];
}

extern "C" void kernel_launch(void* const* d_in, const int* in_sizes, int n_in,
                              void* d_out, int out_size) {
    const float* x  = (const float*)d_in[0];
    const float* rw = (const float*)d_in[1];
    const float* w1 = (const float*)d_in[2];
    const float* b1 = (const float*)d_in[3];
    const float* w2 = (const float*)d_in[4];
    const float* b2 = (const float*)d_in[5];
    float* out = (float*)d_out;

    cudaMemsetAsync(out, 0, (size_t)N_TOK * D_DIM * sizeof(float), 0);

    __half *xh, *w1t, *w2t, *hh;
    cudaGetSymbolAddress((void**)&xh,  g_xh);
    cudaGetSymbolAddress((void**)&w1t, g_w1t);
    cudaGetSymbolAddress((void**)&w2t, g_w2t);
    cudaGetSymbolAddress((void**)&hh,  g_hh);

    // staging: fp16 x; fp16 transposed weights (K-major for mma B-col frags)
    cvt_x_f16_kernel<<<2048, 256>>>(x);
    transpose_cvt_f16_kernel<<<dim3(F_DIM / 32, D_DIM / 32, E_NUM), dim3(32, 8)>>>(
        w1, w1t, D_DIM, F_DIM);   // [d][f] -> [f][d]
    transpose_cvt_f16_kernel<<<dim3(D_DIM / 32, F_DIM / 32, E_NUM), dim3(32, 8)>>>(
        w2, w2t, F_DIM, D_DIM);   // [f][d] -> [d][f]

    router_kernel<<<N_TOK, 256>>>(x, rw);

    cudaFuncSetAttribute(topk_select_kernel, cudaFuncAttributeMaxDynamicSharedMemorySize,
                         N_TOK * sizeof(unsigned long long));
    topk_select_kernel<<<E_NUM, 1024, N_TOK * sizeof(unsigned long long)>>>();

    cudaFuncSetAttribute((const void*)moe_gemm_kernel<D_DIM, F_DIM, true>,
                         cudaFuncAttributeMaxDynamicSharedMemorySize, SMEM_DYN);
    cudaFuncSetAttribute((const void*)moe_gemm_kernel<F_DIM, D_DIM, false>,
                         cudaFuncAttributeMaxDynamicSharedMemorySize, SMEM_DYN);

    // GEMM1: hh = fp16(gelu(gather(xh) @ w1t^T + b1))
    moe_gemm_kernel<D_DIM, F_DIM, true>
        <<<dim3(F_DIM / 128, K_CAP / 128, E_NUM), 128, SMEM_DYN>>>(xh, w1t, b1, out, hh);
    // GEMM2: out += scatter((hh @ w2t^T + b2) * wts)
    moe_gemm_kernel<F_DIM, D_DIM, false>
        <<<dim3(D_DIM / 128, K_CAP / 128, E_NUM), 128, SMEM_DYN>>>(hh, w2t, b2, out, hh);

    const int R = N_TOK * D_DIM;
    if (out_size >= R + N_TOK * E_NUM) {
        int mode = (out_size >= R + N_TOK * E_NUM + E_NUM * K_CAP) ? 2 : 1;
        tail_kernel<<<(N_TOK * E_NUM + 255) / 256, 256>>>(out, mode);
    }
}

// round 15
// speedup vs baseline: 1.5094x; 1.0089x over previous
#include <cuda_runtime.h>
#include <cuda_fp16.h>
#include <math.h>
#include <stdint.h>

#define N_TOK 8192
#define D_DIM 1024
#define E_NUM 8
#define F_DIM 4096
#define K_CAP 1024

// ---- scratch (device globals: no allocation allowed) ----
__device__ float  g_logits[N_TOK * E_NUM];
__device__ float  g_probsT[E_NUM * N_TOK];
__device__ int    g_sel[E_NUM * K_CAP];
__device__ float  g_wts[E_NUM * K_CAP];
__device__ __half g_xh [(size_t)N_TOK * D_DIM];           // 16 MB
__device__ __half g_w1t[(size_t)E_NUM * F_DIM * D_DIM];   // 64 MB  [e][f][d]
__device__ __half g_w2t[(size_t)E_NUM * D_DIM * F_DIM];   // 64 MB  [e][d][f]
__device__ __half g_hh [(size_t)E_NUM * K_CAP * F_DIM];   // 64 MB  [e][k][f]

// ============================================================ helpers
__device__ __forceinline__ void cp16(uint32_t dst, const void* src) {
    asm volatile("cp.async.cg.shared.global [%0], [%1], 16;" :: "r"(dst), "l"(src));
}
__device__ __forceinline__ uint32_t smem_u32(const void* p) {
    uint32_t a;
    asm("{ .reg .u64 t; cvta.to.shared.u64 t, %1; cvt.u32.u64 %0, t; }"
        : "=r"(a) : "l"(p));
    return a;
}
__device__ __forceinline__ void mma16816(float* c, const uint32_t* a, const uint32_t* b) {
    asm volatile(
        "mma.sync.aligned.m16n8k16.row.col.f32.f16.f16.f32 "
        "{%0,%1,%2,%3}, {%4,%5,%6,%7}, {%8,%9}, {%0,%1,%2,%3};"
        : "+f"(c[0]), "+f"(c[1]), "+f"(c[2]), "+f"(c[3])
        : "r"(a[0]), "r"(a[1]), "r"(a[2]), "r"(a[3]), "r"(b[0]), "r"(b[1]));
}
#define LDSM4(R0, R1, R2, R3, ADDR)                                             \
    asm volatile("ldmatrix.sync.aligned.m8n8.x4.shared.b16 {%0,%1,%2,%3}, [%4];"\
                 : "=r"(R0), "=r"(R1), "=r"(R2), "=r"(R3) : "r"(ADDR))

// ============================================================
// K0a: x f32 -> fp16 (grid-stride float4 -> half4)
// ============================================================
__global__ void cvt_x_f16_kernel(const float* __restrict__ src) {
    size_t stride = (size_t)gridDim.x * blockDim.x;
    size_t n4 = (size_t)N_TOK * D_DIM / 4;
    for (size_t i = (size_t)blockIdx.x * blockDim.x + threadIdx.x; i < n4; i += stride) {
        float4 v = ((const float4*)src)[i];
        __half2 h0 = __floats2half2_rn(v.x, v.y);
        __half2 h1 = __floats2half2_rn(v.z, v.w);
        ((__half2*)g_xh)[2 * i]     = h0;
        ((__half2*)g_xh)[2 * i + 1] = h1;
    }
}

// ============================================================
// K0b: transpose + cvt to fp16: src [E][R][C] f32 -> dst [E][C][R] half
// ============================================================
__global__ void transpose_cvt_f16_kernel(const float* __restrict__ src,
                                         __half* __restrict__ dst, int R, int C) {
    __shared__ float tile[32][33];
    int e = blockIdx.z;
    int c0 = blockIdx.x * 32, r0 = blockIdx.y * 32;
    const float* s = src + (size_t)e * R * C;
    __half* d = dst + (size_t)e * C * R;
    int tx = threadIdx.x, ty = threadIdx.y;
#pragma unroll
    for (int i = 0; i < 32; i += 8)
        tile[ty + i][tx] = s[(size_t)(r0 + ty + i) * C + c0 + tx];
    __syncthreads();
#pragma unroll
    for (int i = 0; i < 32; i += 8)
        d[(size_t)(c0 + ty + i) * R + r0 + tx] = __float2half_rn(tile[tx][ty + i]);
}

// ============================================================
// K1: router logits + softmax. One block per token, float4 single pass.
// ============================================================
__global__ void router_kernel(const float* __restrict__ x,
                              const float* __restrict__ rw) {
    int t = blockIdx.x;
    int tid = threadIdx.x;
    float4 xv = ((const float4*)(x + (size_t)t * D_DIM))[tid];
    float acc[E_NUM];
#pragma unroll
    for (int e = 0; e < E_NUM; e++) {
        float4 wv = ((const float4*)(rw + (size_t)e * D_DIM))[tid];
        float s = xv.x * wv.x;
        s = fmaf(xv.y, wv.y, s);
        s = fmaf(xv.z, wv.z, s);
        acc[e] = fmaf(xv.w, wv.w, s);
    }
    __shared__ float red[E_NUM * 256];
#pragma unroll
    for (int e = 0; e < E_NUM; e++) red[e * 256 + tid] = acc[e];
    __syncthreads();
    for (int s = 128; s > 0; s >>= 1) {
        if (tid < s) {
#pragma unroll
            for (int e = 0; e < E_NUM; e++)
                red[e * 256 + tid] += red[e * 256 + tid + s];
        }
        __syncthreads();
    }
    if (tid == 0) {
        float l[E_NUM];
        float mx = -1e30f;
#pragma unroll
        for (int e = 0; e < E_NUM; e++) {
            l[e] = red[e * 256];
            g_logits[t * E_NUM + e] = l[e];
            mx = fmaxf(mx, l[e]);
        }
        float s = 0.0f;
#pragma unroll
        for (int e = 0; e < E_NUM; e++) { l[e] = expf(l[e] - mx); s += l[e]; }
        float inv = 1.0f / s;
#pragma unroll
        for (int e = 0; e < E_NUM; e++)
            g_probsT[e * N_TOK + t] = l[e] * inv;
    }
}

// ============================================================
// K2: per-expert top-K via radix-select + small bitonic of winners.
// ============================================================
#define TOPK_BINS 4096
__global__ void topk_select_kernel() {
    extern __shared__ unsigned long long cand[];
    __shared__ unsigned hist[TOPK_BINS];
    __shared__ unsigned suf[1024];
    __shared__ unsigned long long outk[K_CAP];
    __shared__ unsigned s_binB, s_need, s_ncand, s_slot, s_coarse;

    int e = blockIdx.x, tid = threadIdx.x;
    const float* p = g_probsT + (size_t)e * N_TOK;

#pragma unroll
    for (int i = 0; i < TOPK_BINS / 1024; i++) hist[tid + i * 1024] = 0;
    if (tid == 0) { s_ncand = 0; s_slot = 0; s_coarse = 0; }
    __syncthreads();

    unsigned fb[8];
#pragma unroll
    for (int k = 0; k < 8; k++) {
        int i = tid + k * 1024;
        fb[k] = __float_as_uint(p[i]);
        atomicAdd(&hist[fb[k] >> 20], 1u);
    }
    __syncthreads();

    unsigned s = hist[4 * tid] + hist[4 * tid + 1] + hist[4 * tid + 2] + hist[4 * tid + 3];
    suf[tid] = s;
    __syncthreads();
    for (int off = 1; off < 1024; off <<= 1) {
        unsigned v = (tid + off < 1024) ? suf[tid + off] : 0;
        __syncthreads();
        suf[tid] += v;
        __syncthreads();
    }
    if (suf[tid] >= K_CAP && (tid == 1023 || suf[tid + 1] < K_CAP)) s_coarse = tid;
    __syncthreads();
    if (tid == 0) {
        unsigned co = s_coarse;
        unsigned above = (co == 1023) ? 0 : suf[co + 1];
        unsigned B = 4 * co, need = 0;
        for (int b = 4 * (int)co + 3; b >= 4 * (int)co; b--) {
            if (above + hist[b] >= K_CAP) { B = (unsigned)b; need = K_CAP - above; break; }
            above += hist[b];
        }
        s_binB = B; s_need = need;
    }
    __syncthreads();
    unsigned B = s_binB, need = s_need;

#pragma unroll
    for (int k = 0; k < 8; k++) {
        int i = tid + k * 1024;
        unsigned b = fb[k] >> 20;
        unsigned long long key =
            ((unsigned long long)fb[k] << 32) | (unsigned)(0xFFFFFFFFu - (unsigned)i);
        if (b > B) {
            unsigned sl = atomicAdd(&s_slot, 1u);
            outk[sl] = key;
        } else if (b == B) {
            unsigned c = atomicAdd(&s_ncand, 1u);
            cand[c] = key;
        }
    }
    __syncthreads();
    unsigned c = s_ncand;
    for (unsigned j = tid; j < c; j += 1024) {
        unsigned long long kj = cand[j];
        unsigned rank = 0;
        for (unsigned l = 0; l < c; l++) rank += (cand[l] > kj);
        if (rank < need) {
            unsigned sl = atomicAdd(&s_slot, 1u);
            outk[sl] = kj;
        }
    }
    __syncthreads();

    for (int k = 2; k <= K_CAP; k <<= 1) {
        for (int j = k >> 1; j > 0; j >>= 1) {
            int ixj = tid ^ j;
            if (ixj > tid) {
                unsigned long long a = outk[tid], bk = outk[ixj];
                bool desc = ((tid & k) == 0);
                if (desc ? (a < bk) : (a > bk)) { outk[tid] = bk; outk[ixj] = a; }
            }
            __syncthreads();
        }
    }
    unsigned long long a = outk[tid];
    g_wts[e * K_CAP + tid] = __uint_as_float((unsigned)(a >> 32));
    g_sel[e * K_CAP + tid] = (int)(0xFFFFFFFFu - (unsigned)(a & 0xFFFFFFFFu));
}

// ============================================================
// fp16 mma.sync GEMM: CTA 128x128, 4 warps (2x2), warp tile 64x64,
// mma.m16n8k16 (f32 accum), k-tile 32, 4-stage cp.async pipeline.
// Fragments loaded via ldmatrix.x4 (16 LDSM per k-tile vs 64 LDS).
// SMEM rows 64B (32 halves), 16B-chunk XOR swizzle c ^ ((row>>1)&3).
// ============================================================
#define STG_BYTES 16384                 // A 8KB + B 8KB
#define NSTAGE 4
#define SMEM_DYN (NSTAGE * STG_BYTES)   // 65536 B

template <int KDIM, int NDIM, bool IS_G1>
__global__ __launch_bounds__(128, 2) void moe_gemm_kernel(
    const __half* __restrict__ A_src, const __half* __restrict__ B_src,
    const float* __restrict__ bias, float* __restrict__ out,
    __half* __restrict__ hout) {
    constexpr int KT = KDIM / 32;

    extern __shared__ char smem[];
    uint32_t sb = smem_u32(smem);

    int e = blockIdx.z, m0 = blockIdx.y * 128, n0 = blockIdx.x * 128;
    int t = threadIdx.x, wid = t >> 5, lane = t & 31;
    int wm = (wid >> 1) * 64, wn = (wid & 1) * 64;
    int lg = lane >> 2, lt = lane & 3;

    // ---- cp.async: thread t owns A row t and B row t (4 chunks of 16B each)
    const __half* aptr;
    if (IS_G1) aptr = A_src + (size_t)g_sel[e * K_CAP + m0 + t] * KDIM;
    else       aptr = A_src + ((size_t)e * K_CAP + m0 + t) * KDIM;
    const __half* bptr = B_src + ((size_t)e * NDIM + n0 + t) * KDIM;
    uint32_t swz[4];
    {
        uint32_t xt = ((uint32_t)t >> 1) & 3;
#pragma unroll
        for (int c = 0; c < 4; c++)
            swz[c] = (uint32_t)t * 64 + (((uint32_t)c ^ xt) << 4);
    }

#define LOAD_STAGE(SLOT, KTILE)                                                 \
    do {                                                                        \
        uint32_t off = (uint32_t)(SLOT) * STG_BYTES;                            \
        size_t kh = (size_t)(KTILE) * 32;                                       \
        _Pragma("unroll")                                                       \
        for (int c = 0; c < 4; c++)                                             \
            cp16(sb + off + swz[c], aptr + kh + c * 8);                         \
        _Pragma("unroll")                                                       \
        for (int c = 0; c < 4; c++)                                             \
            cp16(sb + off + 8192 + swz[c], bptr + kh + c * 8);                  \
        asm volatile("cp.async.commit_group;");                                 \
    } while (0)

    // ---- ldmatrix.x4 lane addressing:
    // tile = lane>>3: bit0 -> +8 rows (fragment row-half), bit1 -> +8 k (chunk half)
    // A regs land as {a0,a1,a2,a3}; B regs as {b0[n],b0[n+8],b1[n],b1[n+8]}.
    uint32_t ldsmA[2], ldsmB[2];
    {
        uint32_t lrow = (uint32_t)lane & 7;
        uint32_t rh = ((uint32_t)lane >> 3) & 1;   // row half
        uint32_t ch = ((uint32_t)lane >> 4) & 1;   // chunk half
        uint32_t rowA = (uint32_t)wm + 8 * rh + lrow;
        uint32_t rowB = (uint32_t)wn + 8 * rh + lrow;
        uint32_t xA = (rowA >> 1) & 3, xB = (rowB >> 1) & 3;
#pragma unroll
        for (int g = 0; g < 2; g++) {
            uint32_t cg = 2 * (uint32_t)g + ch;
            ldsmA[g] = sb + rowA * 64 + ((cg ^ xA) << 4);
            ldsmB[g] = sb + 8192 + rowB * 64 + ((cg ^ xB) << 4);
        }
    }

    float acc[4][8][4];
#pragma unroll
    for (int mi = 0; mi < 4; mi++)
#pragma unroll
        for (int ni = 0; ni < 8; ni++)
#pragma unroll
            for (int r = 0; r < 4; r++) acc[mi][ni][r] = 0.0f;

    LOAD_STAGE(0, 0); LOAD_STAGE(1, 1); LOAD_STAGE(2, 2);

#pragma unroll 1
    for (int kt = 0; kt < KT; kt++) {
        int rem = KT - 1 - kt;
        if (rem >= 2)      asm volatile("cp.async.wait_group 2;");
        else if (rem == 1) asm volatile("cp.async.wait_group 1;");
        else               asm volatile("cp.async.wait_group 0;");
        __syncthreads();
        if (kt + NSTAGE - 1 < KT) LOAD_STAGE((kt + NSTAGE - 1) & (NSTAGE - 1), kt + NSTAGE - 1);

        uint32_t soff = (uint32_t)(kt & (NSTAGE - 1)) * STG_BYTES;

#pragma unroll
        for (int g = 0; g < 2; g++) {
            uint32_t af[4][4], bq[4][4];
#pragma unroll
            for (int mi = 0; mi < 4; mi++)
                LDSM4(af[mi][0], af[mi][1], af[mi][2], af[mi][3],
                      ldsmA[g] + soff + (uint32_t)mi * 1024);
#pragma unroll
            for (int p = 0; p < 4; p++)
                LDSM4(bq[p][0], bq[p][1], bq[p][2], bq[p][3],
                      ldsmB[g] + soff + (uint32_t)p * 1024);
#pragma unroll
            for (int mi = 0; mi < 4; mi++)
#pragma unroll
                for (int p = 0; p < 4; p++) {
                    uint32_t blo[2] = { bq[p][0], bq[p][2] };
                    uint32_t bhi[2] = { bq[p][1], bq[p][3] };
                    mma16816(acc[mi][2 * p],     af[mi], blo);
                    mma16816(acc[mi][2 * p + 1], af[mi], bhi);
                }
        }
    }
#undef LOAD_STAGE

    // ---- epilogue ----
    if (IS_G1) {
#pragma unroll
        for (int mi = 0; mi < 4; mi++) {
            int m = m0 + wm + mi * 16 + lg;
#pragma unroll
            for (int ni = 0; ni < 8; ni++) {
                int n = n0 + wn + ni * 8 + 2 * lt;
                float b0 = bias[(size_t)e * NDIM + n];
                float b1v = bias[(size_t)e * NDIM + n + 1];
#pragma unroll
                for (int half = 0; half < 2; half++) {
                    int mm = m + half * 8;
                    float v0 = acc[mi][ni][half * 2 + 0] + b0;
                    float v1 = acc[mi][ni][half * 2 + 1] + b1v;
                    v0 = 0.5f * v0 * (1.0f + erff(v0 * 0.70710678118654752f));
                    v1 = 0.5f * v1 * (1.0f + erff(v1 * 0.70710678118654752f));
                    __half2 hv = __floats2half2_rn(v0, v1);
                    *(__half2*)(hout + ((size_t)e * K_CAP + mm) * F_DIM + n) = hv;
                }
            }
        }
    } else {
#pragma unroll
        for (int mi = 0; mi < 4; mi++) {
            int m = m0 + wm + mi * 16 + lg;
            int tok0 = g_sel[e * K_CAP + m];
            int tok1 = g_sel[e * K_CAP + m + 8];
            float w0 = g_wts[e * K_CAP + m];
            float w1v = g_wts[e * K_CAP + m + 8];
#pragma unroll
            for (int ni = 0; ni < 8; ni++) {
                int n = n0 + wn + ni * 8 + 2 * lt;
                float b0 = bias[(size_t)e * NDIM + n];
                float b1v = bias[(size_t)e * NDIM + n + 1];
                atomicAdd(out + (size_t)tok0 * D_DIM + n,     (acc[mi][ni][0] + b0) * w0);
                atomicAdd(out + (size_t)tok0 * D_DIM + n + 1, (acc[mi][ni][1] + b1v) * w0);
                atomicAdd(out + (size_t)tok1 * D_DIM + n,     (acc[mi][ni][2] + b0) * w1v);
                atomicAdd(out + (size_t)tok1 * D_DIM + n + 1, (acc[mi][ni][3] + b1v) * w1v);
            }
        }
    }
}

// ============================================================
// K5: optional extra outputs
// ============================================================
__global__ void tail_kernel(float* __restrict__ out, int mode) {
    int i = blockIdx.x * 256 + threadIdx.x;
    const int R = N_TOK * D_DIM;
    if (mode >= 1 && i < N_TOK * E_NUM) out[R + i] = g_logits[i];
    if (mode >= 2 && i < E_NUM * K_CAP) out[R + N_TOK * E_NUM + i] = (float)g_sel[i];
}

extern "C" void kernel_launch(void* const* d_in, const int* in_sizes, int n_in,
                              void* d_out, int out_size) {
    const float* x  = (const float*)d_in[0];
    const float* rw = (const float*)d_in[1];
    const float* w1 = (const float*)d_in[2];
    const float* b1 = (const float*)d_in[3];
    const float* w2 = (const float*)d_in[4];
    const float* b2 = (const float*)d_in[5];
    float* out = (float*)d_out;

    cudaMemsetAsync(out, 0, (size_t)N_TOK * D_DIM * sizeof(float), 0);

    __half *xh, *w1t, *w2t, *hh;
    cudaGetSymbolAddress((void**)&xh,  g_xh);
    cudaGetSymbolAddress((void**)&w1t, g_w1t);
    cudaGetSymbolAddress((void**)&w2t, g_w2t);
    cudaGetSymbolAddress((void**)&hh,  g_hh);

    // staging: fp16 x; fp16 transposed weights (K-major for mma B-col frags)
    cvt_x_f16_kernel<<<2048, 256>>>(x);
    transpose_cvt_f16_kernel<<<dim3(F_DIM / 32, D_DIM / 32, E_NUM), dim3(32, 8)>>>(
        w1, w1t, D_DIM, F_DIM);   // [d][f] -> [f][d]
    transpose_cvt_f16_kernel<<<dim3(D_DIM / 32, F_DIM / 32, E_NUM), dim3(32, 8)>>>(
        w2, w2t, F_DIM, D_DIM);   // [f][d] -> [d][f]

    router_kernel<<<N_TOK, 256>>>(x, rw);

    cudaFuncSetAttribute(topk_select_kernel, cudaFuncAttributeMaxDynamicSharedMemorySize,
                         N_TOK * sizeof(unsigned long long));
    topk_select_kernel<<<E_NUM, 1024, N_TOK * sizeof(unsigned long long)>>>();

    cudaFuncSetAttribute((const void*)moe_gemm_kernel<D_DIM, F_DIM, true>,
                         cudaFuncAttributeMaxDynamicSharedMemorySize, SMEM_DYN);
    cudaFuncSetAttribute((const void*)moe_gemm_kernel<F_DIM, D_DIM, false>,
                         cudaFuncAttributeMaxDynamicSharedMemorySize, SMEM_DYN);

    // GEMM1: hh = fp16(gelu(gather(xh) @ w1t^T + b1))
    moe_gemm_kernel<D_DIM, F_DIM, true>
        <<<dim3(F_DIM / 128, K_CAP / 128, E_NUM), 128, SMEM_DYN>>>(xh, w1t, b1, out, hh);
    // GEMM2: out += scatter((hh @ w2t^T + b2) * wts)
    moe_gemm_kernel<F_DIM, D_DIM, false>
        <<<dim3(D_DIM / 128, K_CAP / 128, E_NUM), 128, SMEM_DYN>>>(hh, w2t, b2, out, hh);

    const int R = N_TOK * D_DIM;
    if (out_size >= R + N_TOK * E_NUM) {
        int mode = (out_size >= R + N_TOK * E_NUM + E_NUM * K_CAP) ? 2 : 1;
        tail_kernel<<<(N_TOK * E_NUM + 255) / 256, 256>>>(out, mode);
    }
}